// round 10
// baseline (speedup 1.0000x reference)
#include <cuda_runtime.h>
#include <cuda_fp16.h>
#include <mma.h>
#include <cstdint>

using namespace nvcuda;

#define NV   50000
#define ME   10000
#define NNZt 1600000
#define D    128

#define NBLK_E ((ME + 1023) / 1024)   // 10
#define NBLK_V ((NV + 1023) / 1024)   // 49

// ---------------------------------------------------------------------------
// Static device scratch
// ---------------------------------------------------------------------------
__device__ __half g_Xh[NV * D];       // 12.8 MB  fp16 copy of X
__device__ __half g_Xe[ME * D];       // 2.56 MB  edge means (fp16)
__device__ __half g_Xih[NV * D];      // 12.8 MB  mixed vertex features (fp16)
__device__ int    g_histE[ME];
__device__ int    g_histV[NV];
__device__ int    g_offE[ME];
__device__ int    g_offV[NV];
__device__ int    g_curE[ME];
__device__ int    g_curV[NV];
__device__ int    g_vlistE[NNZt];
__device__ int    g_elistV[NNZt];
__device__ int    g_bsumE[64];
__device__ int    g_bsumV[64];

// ---------------------------------------------------------------------------
// Convert X to fp16
// ---------------------------------------------------------------------------
__global__ void convert_kernel(const float* __restrict__ X) {
    int i = blockIdx.x * blockDim.x + threadIdx.x;
    const int n4 = NV * D / 4;
    if (i >= n4) return;
    float4 v = __ldg(&reinterpret_cast<const float4*>(X)[i]);
    __half2 h0 = __floats2half2_rn(v.x, v.y);
    __half2 h1 = __floats2half2_rn(v.z, v.w);
    uint2 o;
    o.x = *reinterpret_cast<unsigned*>(&h0);
    o.y = *reinterpret_cast<unsigned*>(&h1);
    reinterpret_cast<uint2*>(g_Xh)[i] = o;
}

// ---------------------------------------------------------------------------
// Zero an int array (int4 stores)
// ---------------------------------------------------------------------------
__global__ void zero_kernel(int* __restrict__ p, int n4) {
    int i = blockIdx.x * blockDim.x + threadIdx.x;
    if (i < n4) reinterpret_cast<int4*>(p)[i] = make_int4(0, 0, 0, 0);
}

// ---------------------------------------------------------------------------
// Per-array histogram: 4 entries per thread (R4-proven atomics density)
// ---------------------------------------------------------------------------
__global__ void hist1_kernel(const int* __restrict__ idx, int* __restrict__ hist) {
    int i0 = (blockIdx.x * blockDim.x + threadIdx.x) * 4;
    if (i0 >= NNZt) return;
    int4 a = __ldg(reinterpret_cast<const int4*>(idx + i0));
    atomicAdd(&hist[a.x], 1); atomicAdd(&hist[a.y], 1);
    atomicAdd(&hist[a.z], 1); atomicAdd(&hist[a.w], 1);
}

// ---------------------------------------------------------------------------
// Scan phase A: per-block (1024 elems) partial sums.
// ---------------------------------------------------------------------------
__global__ __launch_bounds__(256) void scanA_kernel(const int* __restrict__ hist,
                                                    int n, int* __restrict__ bsum) {
    int bl = blockIdx.x;
    int t = threadIdx.x;
    int i0 = bl * 1024 + t * 4;
    int s = 0;
    if (i0 < n) {
        int4 v = *reinterpret_cast<const int4*>(hist + i0);
        s = v.x + v.y + v.z + v.w;
    }
    __shared__ int sm[256];
    sm[t] = s; __syncthreads();
    for (int d = 128; d > 0; d >>= 1) {
        if (t < d) sm[t] += sm[t + d];
        __syncthreads();
    }
    if (t == 0) bsum[bl] = sm[0];
}

// ---------------------------------------------------------------------------
// Scan phase C: block-sum prefix (<=64 ladder) + local exclusive prefix.
// ---------------------------------------------------------------------------
__global__ __launch_bounds__(256) void scanC_kernel(const int* __restrict__ hist,
                                                    int n, int nblk,
                                                    const int* __restrict__ bsum,
                                                    int* __restrict__ off,
                                                    int* __restrict__ cur) {
    int bl = blockIdx.x;
    int t = threadIdx.x;

    __shared__ int bs[64];
    if (t < 64) bs[t] = (t < nblk) ? bsum[t] : 0;
    __syncthreads();
    for (int d = 1; d < 64; d <<= 1) {
        int x = 0;
        if (t < 64 && t >= d) x = bs[t - d];
        __syncthreads();
        if (t < 64) bs[t] += x;
        __syncthreads();
    }
    int blockoff = (bl > 0) ? bs[bl - 1] : 0;

    int i0 = bl * 1024 + t * 4;
    int4 v = make_int4(0, 0, 0, 0);
    int s = 0;
    if (i0 < n) {
        v = *reinterpret_cast<const int4*>(hist + i0);
        s = v.x + v.y + v.z + v.w;
    }
    __shared__ int sm[256];
    sm[t] = s; __syncthreads();
    for (int d = 1; d < 256; d <<= 1) {
        int x = (t >= d) ? sm[t - d] : 0;
        __syncthreads();
        sm[t] += x;
        __syncthreads();
    }
    if (i0 < n) {
        int run = blockoff + sm[t] - s;  // exclusive prefix
        int4 o;
        o.x = run; run += v.x;
        o.y = run; run += v.y;
        o.z = run; run += v.z;
        o.w = run;
        *reinterpret_cast<int4*>(off + i0) = o;
        *reinterpret_cast<int4*>(cur + i0) = o;
    }
}

// ---------------------------------------------------------------------------
// Per-array permute: group `val` by `key`: list[atomicAdd(cur[key])] = val.
// 4 entries per thread (R4-proven).
// ---------------------------------------------------------------------------
__global__ void permute1_kernel(const int* __restrict__ key,
                                const int* __restrict__ val,
                                int* __restrict__ cur,
                                int* __restrict__ list) {
    int i0 = (blockIdx.x * blockDim.x + threadIdx.x) * 4;
    if (i0 >= NNZt) return;
    int4 k4 = __ldg(reinterpret_cast<const int4*>(key + i0));
    int4 v4 = __ldg(reinterpret_cast<const int4*>(val + i0));
    int p0 = atomicAdd(&cur[k4.x], 1);
    int p1 = atomicAdd(&cur[k4.y], 1);
    int p2 = atomicAdd(&cur[k4.z], 1);
    int p3 = atomicAdd(&cur[k4.w], 1);
    list[p0] = v4.x; list[p1] = v4.y;
    list[p2] = v4.z; list[p3] = v4.w;
}

// ---------------------------------------------------------------------------
// Pass 1: Xe[e] = mean over incident vertices of Xh[v] (fp16 rows, 256B).
// ---------------------------------------------------------------------------
__global__ __launch_bounds__(256) void pass1_kernel() {
    int e = blockIdx.x * (blockDim.x >> 5) + (threadIdx.x >> 5);
    if (e >= ME) return;
    int lane = threadIdx.x & 31;
    int beg = g_offE[e];
    int cnt = g_histE[e];
    const uint2* X2 = reinterpret_cast<const uint2*>(g_Xh);

    float4 acc = make_float4(0.f, 0.f, 0.f, 0.f);
    for (int base = 0; base < cnt; base += 32) {
        int m = cnt - base; if (m > 32) m = 32;
        int idx = 0;
        if (base + lane < cnt) idx = __ldg(&g_vlistE[beg + base + lane]);
        if (m == 32) {
#pragma unroll 8
            for (int j = 0; j < 32; j++) {
                int v = __shfl_sync(0xffffffffu, idx, j);
                uint2 d = __ldg(&X2[(size_t)v * 32 + lane]);
                float2 f0 = __half22float2(*reinterpret_cast<__half2*>(&d.x));
                float2 f1 = __half22float2(*reinterpret_cast<__half2*>(&d.y));
                acc.x += f0.x; acc.y += f0.y; acc.z += f1.x; acc.w += f1.y;
            }
        } else {
            for (int j = 0; j < m; j++) {
                int v = __shfl_sync(0xffffffffu, idx, j);
                uint2 d = __ldg(&X2[(size_t)v * 32 + lane]);
                float2 f0 = __half22float2(*reinterpret_cast<__half2*>(&d.x));
                float2 f1 = __half22float2(*reinterpret_cast<__half2*>(&d.y));
                acc.x += f0.x; acc.y += f0.y; acc.z += f1.x; acc.w += f1.y;
            }
        }
    }
    float s = (cnt > 0) ? 1.0f / (float)cnt : 0.0f;
    __half2 h0 = __floats2half2_rn(acc.x * s, acc.y * s);
    __half2 h1 = __floats2half2_rn(acc.z * s, acc.w * s);
    uint2 o;
    o.x = *reinterpret_cast<unsigned*>(&h0);
    o.y = *reinterpret_cast<unsigned*>(&h1);
    reinterpret_cast<uint2*>(g_Xe)[(size_t)e * 32 + lane] = o;
}

// ---------------------------------------------------------------------------
// Pass 2 (fused mix): Xi[n] = (1-alpha) * mean_e Xe[e] + alpha * X0[n].
// ---------------------------------------------------------------------------
__global__ __launch_bounds__(256) void pass2_kernel(const float* __restrict__ X0,
                                                    const float* __restrict__ pAlpha) {
    int n = blockIdx.x * (blockDim.x >> 5) + (threadIdx.x >> 5);
    if (n >= NV) return;
    int lane = threadIdx.x & 31;
    int beg = g_offV[n];
    int cnt = g_histV[n];
    const uint2* E2 = reinterpret_cast<const uint2*>(g_Xe);

    float4 acc = make_float4(0.f, 0.f, 0.f, 0.f);
    for (int base = 0; base < cnt; base += 32) {
        int m = cnt - base; if (m > 32) m = 32;
        int idx = 0;
        if (base + lane < cnt) idx = __ldg(&g_elistV[beg + base + lane]);
        if (m == 32) {
#pragma unroll 8
            for (int j = 0; j < 32; j++) {
                int e = __shfl_sync(0xffffffffu, idx, j);
                uint2 d = __ldg(&E2[(size_t)e * 32 + lane]);
                float2 f0 = __half22float2(*reinterpret_cast<__half2*>(&d.x));
                float2 f1 = __half22float2(*reinterpret_cast<__half2*>(&d.y));
                acc.x += f0.x; acc.y += f0.y; acc.z += f1.x; acc.w += f1.y;
            }
        } else {
            for (int j = 0; j < m; j++) {
                int e = __shfl_sync(0xffffffffu, idx, j);
                uint2 d = __ldg(&E2[(size_t)e * 32 + lane]);
                float2 f0 = __half22float2(*reinterpret_cast<__half2*>(&d.x));
                float2 f1 = __half22float2(*reinterpret_cast<__half2*>(&d.y));
                acc.x += f0.x; acc.y += f0.y; acc.z += f1.x; acc.w += f1.y;
            }
        }
    }
    float alpha = __ldg(pAlpha);
    float s = (cnt > 0) ? (1.0f - alpha) / (float)cnt : 0.0f;
    float4 x0 = __ldg(&reinterpret_cast<const float4*>(X0)[(size_t)n * 32 + lane]);
    __half2 h0 = __floats2half2_rn(acc.x * s + alpha * x0.x,
                                   acc.y * s + alpha * x0.y);
    __half2 h1 = __floats2half2_rn(acc.z * s + alpha * x0.z,
                                   acc.w * s + alpha * x0.w);
    uint2 o;
    o.x = *reinterpret_cast<unsigned*>(&h0);
    o.y = *reinterpret_cast<unsigned*>(&h1);
    reinterpret_cast<uint2*>(g_Xih)[(size_t)n * 32 + lane] = o;
}

// ---------------------------------------------------------------------------
// Final (HMMA, R7-proven): out = Xi @ Weff^T,  Weff = (1-beta)*I + beta*W.
// ---------------------------------------------------------------------------
#define GR 64

__global__ __launch_bounds__(256) void final_kernel(
    const float* __restrict__ W,
    const float* __restrict__ pBeta,
    float* __restrict__ out) {
    __shared__ __half Ws[D * D];  // Weff[c][k] row-major, 32 KB

    const float beta = __ldg(pBeta);
    const float omb  = 1.0f - beta;
    const int tid = threadIdx.x;

    for (int idx = tid; idx < D * D; idx += 256) {
        int c = idx >> 7;
        int k = idx & 127;
        float w = beta * __ldg(W + idx) + ((c == k) ? omb : 0.0f);
        Ws[idx] = __float2half(w);
    }
    __syncthreads();

    const int warp = tid >> 5;
    const int wrow = warp >> 1;
    const int wcol = (warp & 1) * 4;
    const int row0 = blockIdx.x * GR + wrow * 16;
    if (row0 + 16 > NV) return;

    wmma::fragment<wmma::accumulator, 16, 16, 16, float> c_frag[4];
#pragma unroll
    for (int j = 0; j < 4; j++) wmma::fill_fragment(c_frag[j], 0.0f);

    const __half* A = g_Xih;
#pragma unroll
    for (int k = 0; k < 8; k++) {
        wmma::fragment<wmma::matrix_a, 16, 16, 16, __half, wmma::row_major> a_frag;
        wmma::load_matrix_sync(a_frag, A + (size_t)row0 * D + k * 16, D);
#pragma unroll
        for (int j = 0; j < 4; j++) {
            wmma::fragment<wmma::matrix_b, 16, 16, 16, __half, wmma::col_major> b_frag;
            wmma::load_matrix_sync(b_frag, Ws + (wcol + j) * 16 * D + k * 16, D);
            wmma::mma_sync(c_frag[j], a_frag, b_frag, c_frag[j]);
        }
    }

#pragma unroll
    for (int j = 0; j < 4; j++) {
        wmma::store_matrix_sync(out + (size_t)row0 * D + (wcol + j) * 16,
                                c_frag[j], D, wmma::mem_row_major);
    }
}

// ---------------------------------------------------------------------------
// Launch: fork/join across 3 concurrent chains (capturable pattern).
//   origin stream: E-chain (zero,hist,scanA,scanC,permute) -> pass1
//   s1:            V-chain (zero,hist,scanA,scanC,permute)
//   s2:            convert X -> fp16
//   join: pass1 waits s2; pass2 waits s1; final last.
// ---------------------------------------------------------------------------
extern "C" void kernel_launch(void* const* d_in, const int* in_sizes, int n_in,
                              void* d_out, int out_size) {
    const float* X      = (const float*)d_in[0];
    const float* X0     = (const float*)d_in[1];
    const float* W      = (const float*)d_in[2];
    const float* pAlpha = (const float*)d_in[3];
    const float* pBeta  = (const float*)d_in[4];
    const int*   vertex = (const int*)d_in[5];
    const int*   edges  = (const int*)d_in[6];
    float* out = (float*)d_out;

    static cudaStream_t s1 = nullptr, s2 = nullptr;
    static cudaEvent_t evRoot = nullptr, evV = nullptr, evX = nullptr;
    if (s1 == nullptr) {
        cudaStreamCreateWithFlags(&s1, cudaStreamNonBlocking);
        cudaStreamCreateWithFlags(&s2, cudaStreamNonBlocking);
        cudaEventCreateWithFlags(&evRoot, cudaEventDisableTiming);
        cudaEventCreateWithFlags(&evV, cudaEventDisableTiming);
        cudaEventCreateWithFlags(&evX, cudaEventDisableTiming);
    }

    int histE_p = nullptr != nullptr;  (void)histE_p;

    // Resolve device-symbol addresses host-side is not allowed without API in
    // capture; kernels reference the globals directly, so wrappers pass them
    // via small launcher kernels taking no pointers. For zero/hist/scan/permute
    // we need raw pointers — obtain once via cudaGetSymbolAddress (host API,
    // not captured, cached statically).
    static int *pHistE = nullptr, *pHistV = nullptr, *pOffE = nullptr,
               *pOffV = nullptr, *pCurE = nullptr, *pCurV = nullptr,
               *pVlistE = nullptr, *pElistV = nullptr, *pBsumE = nullptr,
               *pBsumV = nullptr;
    if (pHistE == nullptr) {
        cudaGetSymbolAddress((void**)&pHistE,  g_histE);
        cudaGetSymbolAddress((void**)&pHistV,  g_histV);
        cudaGetSymbolAddress((void**)&pOffE,   g_offE);
        cudaGetSymbolAddress((void**)&pOffV,   g_offV);
        cudaGetSymbolAddress((void**)&pCurE,   g_curE);
        cudaGetSymbolAddress((void**)&pCurV,   g_curV);
        cudaGetSymbolAddress((void**)&pVlistE, g_vlistE);
        cudaGetSymbolAddress((void**)&pElistV, g_elistV);
        cudaGetSymbolAddress((void**)&pBsumE,  g_bsumE);
        cudaGetSymbolAddress((void**)&pBsumV,  g_bsumV);
    }

    // Fork
    cudaEventRecord(evRoot, 0);
    cudaStreamWaitEvent(s1, evRoot, 0);
    cudaStreamWaitEvent(s2, evRoot, 0);

    // s2: convert X -> fp16
    convert_kernel<<<(NV * D / 4 + 255) / 256, 256, 0, s2>>>(X);
    cudaEventRecord(evX, s2);

    // s1: V-chain
    zero_kernel<<<(NV / 4 + 255) / 256, 256, 0, s1>>>(pHistV, NV / 4);
    hist1_kernel<<<(NNZt / 4 + 255) / 256, 256, 0, s1>>>(vertex, pHistV);
    scanA_kernel<<<NBLK_V, 256, 0, s1>>>(pHistV, NV, pBsumV);
    scanC_kernel<<<NBLK_V, 256, 0, s1>>>(pHistV, NV, NBLK_V, pBsumV, pOffV, pCurV);
    permute1_kernel<<<(NNZt / 4 + 255) / 256, 256, 0, s1>>>(vertex, edges, pCurV, pElistV);
    cudaEventRecord(evV, s1);

    // origin: E-chain
    zero_kernel<<<(ME / 4 + 255) / 256, 256>>>(pHistE, ME / 4);
    hist1_kernel<<<(NNZt / 4 + 255) / 256, 256>>>(edges, pHistE);
    scanA_kernel<<<NBLK_E, 256>>>(pHistE, ME, pBsumE);
    scanC_kernel<<<NBLK_E, 256>>>(pHistE, ME, NBLK_E, pBsumE, pOffE, pCurE);
    permute1_kernel<<<(NNZt / 4 + 255) / 256, 256>>>(edges, vertex, pCurE, pVlistE);

    // pass1 needs E-lists (origin) + Xh (s2)
    cudaStreamWaitEvent(0, evX, 0);
    pass1_kernel<<<(ME * 32 + 255) / 256, 256>>>();

    // pass2 needs Xe (origin) + V-lists (s1)
    cudaStreamWaitEvent(0, evV, 0);
    pass2_kernel<<<(NV * 32 + 255) / 256, 256>>>(X0, pAlpha);

    final_kernel<<<(NV + GR - 1) / GR, 256>>>(W, pBeta, out);
}

// round 12
// speedup vs baseline: 1.5341x; 1.5341x over previous
#include <cuda_runtime.h>
#include <cuda_fp16.h>
#include <mma.h>
#include <cstdint>

using namespace nvcuda;

#define NV   50000
#define ME   10000
#define NNZt 1600000
#define D    128

#define NBLK_E ((ME + 1023) / 1024)   // 10
#define NBLK_V ((NV + 1023) / 1024)   // 49
#define PB1    (ME / 8)               // 1250 pass1 blocks (8 edges/block)
#define PBV    ((NNZt / 4 + 255) / 256)  // 1563 permuteV blocks

// ---------------------------------------------------------------------------
// Static device scratch
// ---------------------------------------------------------------------------
__device__ __half g_Xh[NV * D];       // 12.8 MB  fp16 copy of X
__device__ __half g_Xe[ME * D];       // 2.56 MB  edge means (fp16)
__device__ __half g_Xih[NV * D];      // 12.8 MB  mixed vertex features (fp16)
__device__ int    g_histE[ME];
__device__ int    g_histV[NV];
__device__ int    g_offE[ME];
__device__ int    g_offV[NV];
__device__ int    g_curE[ME];
__device__ int    g_curV[NV];
__device__ int    g_vlistE[NNZt];
__device__ int    g_elistV[NNZt];
__device__ int    g_bsumE[64];
__device__ int    g_bsumV[64];

// ---------------------------------------------------------------------------
// Prep: convert X to fp16 AND zero histograms (fused, R9-proven)
// ---------------------------------------------------------------------------
__global__ void prep_kernel(const float* __restrict__ X) {
    int i = blockIdx.x * blockDim.x + threadIdx.x;
    const int n4 = NV * D / 4;
    if (i < n4) {
        float4 v = __ldg(&reinterpret_cast<const float4*>(X)[i]);
        __half2 h0 = __floats2half2_rn(v.x, v.y);
        __half2 h1 = __floats2half2_rn(v.z, v.w);
        uint2 o;
        o.x = *reinterpret_cast<unsigned*>(&h0);
        o.y = *reinterpret_cast<unsigned*>(&h1);
        reinterpret_cast<uint2*>(g_Xh)[i] = o;
    }
    if (i < ME) g_histE[i] = 0;
    if (i < NV) g_histV[i] = 0;
}

// ---------------------------------------------------------------------------
// Histogram: combined E+V, 4 entries per thread = 8 independent atomic
// chains (R4-proven configuration)
// ---------------------------------------------------------------------------
__global__ void hist_kernel(const int* __restrict__ vertex,
                            const int* __restrict__ edges) {
    int i0 = (blockIdx.x * blockDim.x + threadIdx.x) * 4;
    if (i0 >= NNZt) return;
    int4 v4 = __ldg(reinterpret_cast<const int4*>(vertex + i0));
    int4 e4 = __ldg(reinterpret_cast<const int4*>(edges + i0));
    atomicAdd(&g_histE[e4.x], 1); atomicAdd(&g_histE[e4.y], 1);
    atomicAdd(&g_histE[e4.z], 1); atomicAdd(&g_histE[e4.w], 1);
    atomicAdd(&g_histV[v4.x], 1); atomicAdd(&g_histV[v4.y], 1);
    atomicAdd(&g_histV[v4.z], 1); atomicAdd(&g_histV[v4.w], 1);
}

// ---------------------------------------------------------------------------
// Scan phase A: per-block (1024 elems) partial sums (R9-proven).
// ---------------------------------------------------------------------------
__global__ __launch_bounds__(256) void scanA_kernel() {
    int b = blockIdx.x;
    const int* hist; int n, bl; int* bsum;
    if (b < NBLK_E) { hist = g_histE; n = ME; bl = b;          bsum = g_bsumE; }
    else            { hist = g_histV; n = NV; bl = b - NBLK_E; bsum = g_bsumV; }
    int t = threadIdx.x;
    int i0 = bl * 1024 + t * 4;
    int s = 0;
    if (i0 < n) {
        int4 v = *reinterpret_cast<const int4*>(hist + i0);
        s = v.x + v.y + v.z + v.w;
    }
    __shared__ int sm[256];
    sm[t] = s; __syncthreads();
    for (int d = 128; d > 0; d >>= 1) {
        if (t < d) sm[t] += sm[t + d];
        __syncthreads();
    }
    if (t == 0) bsum[bl] = sm[0];
}

// ---------------------------------------------------------------------------
// Scan phase C (scanB fused, R9-proven at ~5.5us).
// ---------------------------------------------------------------------------
__global__ __launch_bounds__(256) void scanC_kernel() {
    int b = blockIdx.x;
    const int* hist; int n, bl; int *off, *cur; const int* bsum;
    if (b < NBLK_E) { hist = g_histE; n = ME; bl = b;          off = g_offE; cur = g_curE; bsum = g_bsumE; }
    else            { hist = g_histV; n = NV; bl = b - NBLK_E; off = g_offV; cur = g_curV; bsum = g_bsumV; }
    int t = threadIdx.x;
    int nblk = (b < NBLK_E) ? NBLK_E : NBLK_V;

    __shared__ int bs[64];
    if (t < 64) bs[t] = (t < nblk) ? bsum[t] : 0;
    __syncthreads();
    for (int d = 1; d < 64; d <<= 1) {
        int x = 0;
        if (t < 64 && t >= d) x = bs[t - d];
        __syncthreads();
        if (t < 64) bs[t] += x;
        __syncthreads();
    }
    int blockoff = (bl > 0) ? bs[bl - 1] : 0;

    int i0 = bl * 1024 + t * 4;
    int4 v = make_int4(0, 0, 0, 0);
    int s = 0;
    if (i0 < n) {
        v = *reinterpret_cast<const int4*>(hist + i0);
        s = v.x + v.y + v.z + v.w;
    }
    __shared__ int sm[256];
    sm[t] = s; __syncthreads();
    for (int d = 1; d < 256; d <<= 1) {
        int x = (t >= d) ? sm[t - d] : 0;
        __syncthreads();
        sm[t] += x;
        __syncthreads();
    }
    if (i0 < n) {
        int run = blockoff + sm[t] - s;  // exclusive prefix
        int4 o;
        o.x = run; run += v.x;
        o.y = run; run += v.y;
        o.z = run; run += v.z;
        o.w = run;
        *reinterpret_cast<int4*>(off + i0) = o;
        *reinterpret_cast<int4*>(cur + i0) = o;
    }
}

// ---------------------------------------------------------------------------
// Permute E-side only: vlistE[curE[e]++] = v. 4 entries/thread.
// (Must complete before pass1; the V-side is fused into the next kernel.)
// ---------------------------------------------------------------------------
__global__ void permuteE_kernel(const int* __restrict__ vertex,
                                const int* __restrict__ edges) {
    int i0 = (blockIdx.x * blockDim.x + threadIdx.x) * 4;
    if (i0 >= NNZt) return;
    int4 v4 = __ldg(reinterpret_cast<const int4*>(vertex + i0));
    int4 e4 = __ldg(reinterpret_cast<const int4*>(edges + i0));
    int p0 = atomicAdd(&g_curE[e4.x], 1);
    int p1 = atomicAdd(&g_curE[e4.y], 1);
    int p2 = atomicAdd(&g_curE[e4.z], 1);
    int p3 = atomicAdd(&g_curE[e4.w], 1);
    g_vlistE[p0] = v4.x; g_vlistE[p1] = v4.y;
    g_vlistE[p2] = v4.z; g_vlistE[p3] = v4.w;
}

// ---------------------------------------------------------------------------
// Fused pass1 + permuteV (block-partitioned, no cross-block dependency):
//   blocks [0, PB1):      pass1 — Xe[e] = mean_v Xh[v]  (warp per edge)
//   blocks [PB1, +PBV):   permuteV — elistV[curV[v]++] = e
// The V-side atomics execute in pass1's L2-latency shadow.
// ---------------------------------------------------------------------------
__global__ __launch_bounds__(256) void pass1_permV_kernel(
    const int* __restrict__ vertex,
    const int* __restrict__ edges) {
    if (blockIdx.x < PB1) {
        // ---- pass1 (R9-proven body) ----
        int e = blockIdx.x * 8 + (threadIdx.x >> 5);
        int lane = threadIdx.x & 31;
        int beg = g_offE[e];
        int cnt = g_histE[e];
        const uint2* X2 = reinterpret_cast<const uint2*>(g_Xh);

        float4 acc = make_float4(0.f, 0.f, 0.f, 0.f);
        for (int base = 0; base < cnt; base += 32) {
            int m = cnt - base; if (m > 32) m = 32;
            int idx = 0;
            if (base + lane < cnt) idx = __ldg(&g_vlistE[beg + base + lane]);
            if (m == 32) {
#pragma unroll 8
                for (int j = 0; j < 32; j++) {
                    int v = __shfl_sync(0xffffffffu, idx, j);
                    uint2 d = __ldg(&X2[(size_t)v * 32 + lane]);
                    float2 f0 = __half22float2(*reinterpret_cast<__half2*>(&d.x));
                    float2 f1 = __half22float2(*reinterpret_cast<__half2*>(&d.y));
                    acc.x += f0.x; acc.y += f0.y; acc.z += f1.x; acc.w += f1.y;
                }
            } else {
                for (int j = 0; j < m; j++) {
                    int v = __shfl_sync(0xffffffffu, idx, j);
                    uint2 d = __ldg(&X2[(size_t)v * 32 + lane]);
                    float2 f0 = __half22float2(*reinterpret_cast<__half2*>(&d.x));
                    float2 f1 = __half22float2(*reinterpret_cast<__half2*>(&d.y));
                    acc.x += f0.x; acc.y += f0.y; acc.z += f1.x; acc.w += f1.y;
                }
            }
        }
        float s = (cnt > 0) ? 1.0f / (float)cnt : 0.0f;
        __half2 h0 = __floats2half2_rn(acc.x * s, acc.y * s);
        __half2 h1 = __floats2half2_rn(acc.z * s, acc.w * s);
        uint2 o;
        o.x = *reinterpret_cast<unsigned*>(&h0);
        o.y = *reinterpret_cast<unsigned*>(&h1);
        reinterpret_cast<uint2*>(g_Xe)[(size_t)e * 32 + lane] = o;
    } else {
        // ---- permuteV (independent of pass1) ----
        int i0 = ((blockIdx.x - PB1) * 256 + threadIdx.x) * 4;
        if (i0 >= NNZt) return;
        int4 v4 = __ldg(reinterpret_cast<const int4*>(vertex + i0));
        int4 e4 = __ldg(reinterpret_cast<const int4*>(edges + i0));
        int q0 = atomicAdd(&g_curV[v4.x], 1);
        int q1 = atomicAdd(&g_curV[v4.y], 1);
        int q2 = atomicAdd(&g_curV[v4.z], 1);
        int q3 = atomicAdd(&g_curV[v4.w], 1);
        g_elistV[q0] = e4.x; g_elistV[q1] = e4.y;
        g_elistV[q2] = e4.z; g_elistV[q3] = e4.w;
    }
}

// ---------------------------------------------------------------------------
// Pass 2 (fused mix, R9-proven): Xi[n] = (1-a)*mean_e Xe[e] + a*X0[n], fp16.
// ---------------------------------------------------------------------------
__global__ __launch_bounds__(256) void pass2_kernel(const float* __restrict__ X0,
                                                    const float* __restrict__ pAlpha) {
    int n = blockIdx.x * (blockDim.x >> 5) + (threadIdx.x >> 5);
    if (n >= NV) return;
    int lane = threadIdx.x & 31;
    int beg = g_offV[n];
    int cnt = g_histV[n];
    const uint2* E2 = reinterpret_cast<const uint2*>(g_Xe);

    float4 acc = make_float4(0.f, 0.f, 0.f, 0.f);
    for (int base = 0; base < cnt; base += 32) {
        int m = cnt - base; if (m > 32) m = 32;
        int idx = 0;
        if (base + lane < cnt) idx = __ldg(&g_elistV[beg + base + lane]);
        if (m == 32) {
#pragma unroll 8
            for (int j = 0; j < 32; j++) {
                int e = __shfl_sync(0xffffffffu, idx, j);
                uint2 d = __ldg(&E2[(size_t)e * 32 + lane]);
                float2 f0 = __half22float2(*reinterpret_cast<__half2*>(&d.x));
                float2 f1 = __half22float2(*reinterpret_cast<__half2*>(&d.y));
                acc.x += f0.x; acc.y += f0.y; acc.z += f1.x; acc.w += f1.y;
            }
        } else {
            for (int j = 0; j < m; j++) {
                int e = __shfl_sync(0xffffffffu, idx, j);
                uint2 d = __ldg(&E2[(size_t)e * 32 + lane]);
                float2 f0 = __half22float2(*reinterpret_cast<__half2*>(&d.x));
                float2 f1 = __half22float2(*reinterpret_cast<__half2*>(&d.y));
                acc.x += f0.x; acc.y += f0.y; acc.z += f1.x; acc.w += f1.y;
            }
        }
    }
    float alpha = __ldg(pAlpha);
    float s = (cnt > 0) ? (1.0f - alpha) / (float)cnt : 0.0f;
    float4 x0 = __ldg(&reinterpret_cast<const float4*>(X0)[(size_t)n * 32 + lane]);
    __half2 h0 = __floats2half2_rn(acc.x * s + alpha * x0.x,
                                   acc.y * s + alpha * x0.y);
    __half2 h1 = __floats2half2_rn(acc.z * s + alpha * x0.z,
                                   acc.w * s + alpha * x0.w);
    uint2 o;
    o.x = *reinterpret_cast<unsigned*>(&h0);
    o.y = *reinterpret_cast<unsigned*>(&h1);
    reinterpret_cast<uint2*>(g_Xih)[(size_t)n * 32 + lane] = o;
}

// ---------------------------------------------------------------------------
// Final (HMMA, R7-proven): out = Xi @ Weff^T,  Weff = (1-beta)*I + beta*W.
// ---------------------------------------------------------------------------
#define GR 64

__global__ __launch_bounds__(256) void final_kernel(
    const float* __restrict__ W,
    const float* __restrict__ pBeta,
    float* __restrict__ out) {
    __shared__ __half Ws[D * D];  // Weff[c][k] row-major, 32 KB

    const float beta = __ldg(pBeta);
    const float omb  = 1.0f - beta;
    const int tid = threadIdx.x;

    for (int idx = tid; idx < D * D; idx += 256) {
        int c = idx >> 7;
        int k = idx & 127;
        float w = beta * __ldg(W + idx) + ((c == k) ? omb : 0.0f);
        Ws[idx] = __float2half(w);
    }
    __syncthreads();

    const int warp = tid >> 5;
    const int wrow = warp >> 1;
    const int wcol = (warp & 1) * 4;
    const int row0 = blockIdx.x * GR + wrow * 16;
    if (row0 + 16 > NV) return;

    wmma::fragment<wmma::accumulator, 16, 16, 16, float> c_frag[4];
#pragma unroll
    for (int j = 0; j < 4; j++) wmma::fill_fragment(c_frag[j], 0.0f);

    const __half* A = g_Xih;
#pragma unroll
    for (int k = 0; k < 8; k++) {
        wmma::fragment<wmma::matrix_a, 16, 16, 16, __half, wmma::row_major> a_frag;
        wmma::load_matrix_sync(a_frag, A + (size_t)row0 * D + k * 16, D);
#pragma unroll
        for (int j = 0; j < 4; j++) {
            wmma::fragment<wmma::matrix_b, 16, 16, 16, __half, wmma::col_major> b_frag;
            wmma::load_matrix_sync(b_frag, Ws + (wcol + j) * 16 * D + k * 16, D);
            wmma::mma_sync(c_frag[j], a_frag, b_frag, c_frag[j]);
        }
    }

#pragma unroll
    for (int j = 0; j < 4; j++) {
        wmma::store_matrix_sync(out + (size_t)row0 * D + (wcol + j) * 16,
                                c_frag[j], D, wmma::mem_row_major);
    }
}

// ---------------------------------------------------------------------------
extern "C" void kernel_launch(void* const* d_in, const int* in_sizes, int n_in,
                              void* d_out, int out_size) {
    const float* X      = (const float*)d_in[0];
    const float* X0     = (const float*)d_in[1];
    const float* W      = (const float*)d_in[2];
    const float* pAlpha = (const float*)d_in[3];
    const float* pBeta  = (const float*)d_in[4];
    const int*   vertex = (const int*)d_in[5];
    const int*   edges  = (const int*)d_in[6];
    float* out = (float*)d_out;

    prep_kernel<<<(NV * D / 4 + 255) / 256, 256>>>(X);
    hist_kernel<<<(NNZt / 4 + 255) / 256, 256>>>(vertex, edges);
    scanA_kernel<<<NBLK_E + NBLK_V, 256>>>();
    scanC_kernel<<<NBLK_E + NBLK_V, 256>>>();
    permuteE_kernel<<<(NNZt / 4 + 255) / 256, 256>>>(vertex, edges);

    pass1_permV_kernel<<<PB1 + PBV, 256>>>(vertex, edges);
    pass2_kernel<<<(NV * 32 + 255) / 256, 256>>>(X0, pAlpha);

    final_kernel<<<(NV + GR - 1) / GR, 256>>>(W, pBeta, out);
}